// round 1
// baseline (speedup 1.0000x reference)
#include <cuda_runtime.h>

#define NB 32768   // batch rows
#define ND 512     // feature dim
#define NK 8192    // codebook size

// Scratch (device globals: no allocation allowed in kernel_launch)
__device__ float g_znorm[NB];
__device__ float g_wnorm[NK];
__device__ int   g_bestidx[NB];
__device__ float g_partials[NB];

// ---------------------------------------------------------------------------
// Row squared-norms, strictly sequential fp32 mul-then-add (emulates the
// reference's elementwise z*z followed by a sum reduction; no FMA contraction).
// ---------------------------------------------------------------------------
__global__ void rownorm_z(const float* __restrict__ x) {
    int r = blockIdx.x * blockDim.x + threadIdx.x;
    if (r >= NB) return;
    const float4* p = reinterpret_cast<const float4*>(x + (size_t)r * ND);
    float acc = 0.f;
#pragma unroll 4
    for (int i = 0; i < ND / 4; i++) {
        float4 v = __ldg(p + i);
        acc = __fadd_rn(acc, __fmul_rn(v.x, v.x));
        acc = __fadd_rn(acc, __fmul_rn(v.y, v.y));
        acc = __fadd_rn(acc, __fmul_rn(v.z, v.z));
        acc = __fadd_rn(acc, __fmul_rn(v.w, v.w));
    }
    g_znorm[r] = acc;
}

__global__ void rownorm_w(const float* __restrict__ x) {
    int r = blockIdx.x * blockDim.x + threadIdx.x;
    if (r >= NK) return;
    const float4* p = reinterpret_cast<const float4*>(x + (size_t)r * ND);
    float acc = 0.f;
#pragma unroll 4
    for (int i = 0; i < ND / 4; i++) {
        float4 v = __ldg(p + i);
        acc = __fadd_rn(acc, __fmul_rn(v.x, v.x));
        acc = __fadd_rn(acc, __fmul_rn(v.y, v.y));
        acc = __fadd_rn(acc, __fmul_rn(v.z, v.z));
        acc = __fadd_rn(acc, __fmul_rn(v.w, v.w));
    }
    g_wnorm[r] = acc;
}

// ---------------------------------------------------------------------------
// Fused distance-GEMM + argmin.
// Block: 64 z-rows x all 8192 codewords (iterated in 128-col tiles).
// 256 threads, 4x8 register tile, BK=8 smem-tiled over D.
// Score uses the reference's rounding: d2 = fl(fl(zn + wn) - fl(2*dot)).
// Tie-break: lowest codeword index (jnp.argmin semantics).
// ---------------------------------------------------------------------------
#define BM 64
#define BN 128
#define BK 8

__global__ __launch_bounds__(256, 3) void vq_argmin(const float* __restrict__ z,
                                                    const float* __restrict__ W) {
    __shared__ float As[BK * BM];
    __shared__ float Bs[BK * BN];
    __shared__ float redv[BM * 16];
    __shared__ int   redi[BM * 16];

    int tid = threadIdx.x;
    int tx = tid & 15;
    int ty = tid >> 4;
    int m0 = blockIdx.x * BM;

    float bestv[4];
    int   besti[4];
#pragma unroll
    for (int i = 0; i < 4; i++) { bestv[i] = __int_as_float(0x7f800000); besti[i] = 0; }

    float zn[4];
#pragma unroll
    for (int i = 0; i < 4; i++) zn[i] = g_znorm[m0 + ty * 4 + i];

    int arow = tid >> 1;          // 0..127 (A uses tid<128 -> arow 0..63)
    int aq   = (tid & 1) * 4;
    int brow = tid >> 1;          // 0..127
    int bq   = (tid & 1) * 4;

    for (int nt = 0; nt < NK / BN; nt++) {
        int n0 = nt * BN;
        float acc[4][8];
#pragma unroll
        for (int i = 0; i < 4; i++)
#pragma unroll
            for (int j = 0; j < 8; j++) acc[i][j] = 0.f;

        for (int kt = 0; kt < ND / BK; kt++) {
            int d0 = kt * BK;
            float4 av = make_float4(0.f, 0.f, 0.f, 0.f);
            if (tid < 128)
                av = *reinterpret_cast<const float4*>(z + (size_t)(m0 + arow) * ND + d0 + aq);
            float4 bv = *reinterpret_cast<const float4*>(W + (size_t)(n0 + brow) * ND + d0 + bq);
            __syncthreads();
            if (tid < 128) {
                As[(aq + 0) * BM + arow] = av.x;
                As[(aq + 1) * BM + arow] = av.y;
                As[(aq + 2) * BM + arow] = av.z;
                As[(aq + 3) * BM + arow] = av.w;
            }
            Bs[(bq + 0) * BN + brow] = bv.x;
            Bs[(bq + 1) * BN + brow] = bv.y;
            Bs[(bq + 2) * BN + brow] = bv.z;
            Bs[(bq + 3) * BN + brow] = bv.w;
            __syncthreads();
#pragma unroll
            for (int d = 0; d < BK; d++) {
                float a[4], b[8];
                float4 a4 = *reinterpret_cast<const float4*>(&As[d * BM + ty * 4]);
                a[0] = a4.x; a[1] = a4.y; a[2] = a4.z; a[3] = a4.w;
                float4 b4 = *reinterpret_cast<const float4*>(&Bs[d * BN + tx * 4]);
                b[0] = b4.x; b[1] = b4.y; b[2] = b4.z; b[3] = b4.w;
                float4 b5 = *reinterpret_cast<const float4*>(&Bs[d * BN + 64 + tx * 4]);
                b[4] = b5.x; b[5] = b5.y; b[6] = b5.z; b[7] = b5.w;
#pragma unroll
                for (int i = 0; i < 4; i++)
#pragma unroll
                    for (int j = 0; j < 8; j++)
                        acc[i][j] = __fmaf_rn(a[i], b[j], acc[i][j]);
            }
        }
        // Epilogue: score + running argmin. Column order is ascending global
        // index within this thread, so strict < keeps the first (lowest) index.
#pragma unroll
        for (int j = 0; j < 8; j++) {
            int c  = (j < 4) ? (tx * 4 + j) : (64 + tx * 4 + (j - 4));
            int gk = n0 + c;
            float wn = g_wnorm[gk];
#pragma unroll
            for (int i = 0; i < 4; i++) {
                float t1 = __fadd_rn(zn[i], wn);
                float d2 = __fsub_rn(t1, __fmul_rn(2.0f, acc[i][j]));
                if (d2 < bestv[i]) { bestv[i] = d2; besti[i] = gk; }
            }
        }
    }

    // Cross-thread reduction (16 tx entries per row), tie-break lowest index.
#pragma unroll
    for (int i = 0; i < 4; i++) {
        redv[(ty * 4 + i) * 16 + tx] = bestv[i];
        redi[(ty * 4 + i) * 16 + tx] = besti[i];
    }
    __syncthreads();
    if (tid < BM) {
        float bv = redv[tid * 16];
        int   bi = redi[tid * 16];
#pragma unroll
        for (int t = 1; t < 16; t++) {
            float v = redv[tid * 16 + t];
            int  ii = redi[tid * 16 + t];
            if (v < bv || (v == bv && ii < bi)) { bv = v; bi = ii; }
        }
        g_bestidx[m0 + tid] = bi;
    }
}

// ---------------------------------------------------------------------------
// Gather z_q with straight-through rounding emulation, per-row loss partials,
// indices written as float.
// ---------------------------------------------------------------------------
__global__ void gather_out(const float* __restrict__ z, const float* __restrict__ W,
                           float* __restrict__ out, int out_size) {
    int b = blockIdx.x;
    int t = threadIdx.x;
    int idx = g_bestidx[b];
    const float* wr = W + (size_t)idx * ND;
    const float* zr = z + (size_t)b * ND;
    float s = 0.f;
#pragma unroll
    for (int i = 0; i < ND / 128; i++) {
        int j = t + i * 128;
        float wv = wr[j];
        float zv = zr[j];
        float diff = __fsub_rn(wv, zv);               // fl(z_q_raw - z)
        out[(size_t)b * ND + j] = __fadd_rn(zv, diff); // fl(z + fl(z_q_raw - z))
        s = __fmaf_rn(diff, diff, s);
    }
    __shared__ float sm[128];
    sm[t] = s;
    __syncthreads();
    for (int o = 64; o > 0; o >>= 1) {
        if (t < o) sm[t] += sm[t + o];
        __syncthreads();
    }
    if (t == 0) {
        g_partials[b] = sm[0];
        size_t off = (size_t)NB * ND + b;
        if (off < (size_t)out_size) out[off] = (float)idx;
    }
}

__global__ void loss_reduce(float* __restrict__ out, int out_size) {
    __shared__ float sm[256];
    int t = threadIdx.x;
    float s = 0.f;
    for (int i = t; i < NB; i += 256) s += g_partials[i];
    sm[t] = s;
    __syncthreads();
    for (int o = 128; o > 0; o >>= 1) {
        if (t < o) sm[t] += sm[t + o];
        __syncthreads();
    }
    if (t == 0) {
        size_t off = (size_t)NB * ND + NB;
        // vq_loss = q_latent + 0.25*e_latent; both equal mean((W[idx]-z)^2)
        // numerically. Division by 2^24 is exact; *1.25 matches fl(q + 0.25q).
        if (off < (size_t)out_size)
            out[off] = 1.25f * (sm[0] / (float)((size_t)NB * ND));
    }
}

// ---------------------------------------------------------------------------
extern "C" void kernel_launch(void* const* d_in, const int* in_sizes, int n_in,
                              void* d_out, int out_size) {
    const float* z = (const float*)d_in[0];  // [32768, 512]
    const float* W = (const float*)d_in[1];  // [8192, 512]
    float* out = (float*)d_out;              // [z_q | indices | vq_loss]

    rownorm_z<<<NB / 128, 128>>>(z);
    rownorm_w<<<NK / 128, 128>>>(W);
    vq_argmin<<<NB / BM, 256>>>(z, W);
    gather_out<<<NB, 128>>>(z, W, out, out_size);
    loss_reduce<<<1, 256>>>(out, out_size);
}

// round 4
// speedup vs baseline: 6.1026x; 6.1026x over previous
#include <cuda_runtime.h>
#include <cuda_bf16.h>
#include <cstdint>

#define NB 32768
#define ND 512
#define NK 8192
#define CAP 64
#define MARGIN_S 4e-4f

// ---------------- device scratch ----------------
__device__ float g_znorm[NB];
__device__ float g_wnorm[NK];
__device__ int   g_bestidx[NB];
__device__ float g_partials[NB];
__device__ unsigned short g_zb[NB * ND];   // bf16 copies
__device__ unsigned short g_wb[NK * ND];
__device__ int g_cnt[NB];
__device__ int g_cand[NB * CAP];

// ---------------- helpers ----------------
__device__ __forceinline__ uint32_t smem_u32(const void* p) {
    uint32_t a;
    asm("{ .reg .u64 t; cvta.to.shared.u64 t, %1; cvt.u32.u64 %0, t; }" : "=r"(a) : "l"(p));
    return a;
}
__device__ __forceinline__ void cp16(uint32_t s, const void* g) {
    asm volatile("cp.async.cg.shared.global [%0], [%1], 16;" :: "r"(s), "l"(g));
}
__device__ __forceinline__ void cp_commit() { asm volatile("cp.async.commit_group;"); }
template <int N>
__device__ __forceinline__ void cp_wait() { asm volatile("cp.async.wait_group %0;" :: "n"(N)); }

__device__ __forceinline__ void ldmA(uint32_t* f, uint32_t addr) {
    asm volatile("ldmatrix.sync.aligned.m8n8.x4.shared.b16 {%0,%1,%2,%3}, [%4];"
                 : "=r"(f[0]), "=r"(f[1]), "=r"(f[2]), "=r"(f[3]) : "r"(addr));
}
__device__ __forceinline__ void ldmB(uint32_t* f, uint32_t addr) {
    asm volatile("ldmatrix.sync.aligned.m8n8.x2.shared.b16 {%0,%1}, [%2];"
                 : "=r"(f[0]), "=r"(f[1]) : "r"(addr));
}
__device__ __forceinline__ void mma16816(float* c, const uint32_t* a, const uint32_t* b) {
    asm volatile("mma.sync.aligned.m16n8k16.row.col.f32.bf16.bf16.f32 "
                 "{%0,%1,%2,%3}, {%4,%5,%6,%7}, {%8,%9}, {%0,%1,%2,%3};"
                 : "+f"(c[0]), "+f"(c[1]), "+f"(c[2]), "+f"(c[3])
                 : "r"(a[0]), "r"(a[1]), "r"(a[2]), "r"(a[3]), "r"(b[0]), "r"(b[1]));
}
// monotone float<->uint key
__device__ __forceinline__ unsigned fkey(float x) {
    unsigned u = __float_as_uint(x);
    return (u & 0x80000000u) ? ~u : (u | 0x80000000u);
}
__device__ __forceinline__ float fdec(unsigned k) {
    return (k & 0x80000000u) ? __uint_as_float(k & 0x7fffffffu) : __uint_as_float(~k);
}

// ---------------- row norms (exact, sequential) + cnt zero ----------------
__global__ void rownorm_z(const float* __restrict__ x) {
    int r = blockIdx.x * blockDim.x + threadIdx.x;
    if (r >= NB) return;
    const float4* p = reinterpret_cast<const float4*>(x + (size_t)r * ND);
    float acc = 0.f;
#pragma unroll 4
    for (int i = 0; i < ND / 4; i++) {
        float4 v = __ldg(p + i);
        acc = __fadd_rn(acc, __fmul_rn(v.x, v.x));
        acc = __fadd_rn(acc, __fmul_rn(v.y, v.y));
        acc = __fadd_rn(acc, __fmul_rn(v.z, v.z));
        acc = __fadd_rn(acc, __fmul_rn(v.w, v.w));
    }
    g_znorm[r] = acc;
    g_cnt[r] = 0;
}
__global__ void rownorm_w(const float* __restrict__ x) {
    int r = blockIdx.x * blockDim.x + threadIdx.x;
    if (r >= NK) return;
    const float4* p = reinterpret_cast<const float4*>(x + (size_t)r * ND);
    float acc = 0.f;
#pragma unroll 4
    for (int i = 0; i < ND / 4; i++) {
        float4 v = __ldg(p + i);
        acc = __fadd_rn(acc, __fmul_rn(v.x, v.x));
        acc = __fadd_rn(acc, __fmul_rn(v.y, v.y));
        acc = __fadd_rn(acc, __fmul_rn(v.z, v.z));
        acc = __fadd_rn(acc, __fmul_rn(v.w, v.w));
    }
    g_wnorm[r] = acc;
}

// ---------------- fp32 -> bf16 convert ----------------
__global__ void conv_bf16(const float* __restrict__ src, unsigned short* dst, int n8) {
    int i = blockIdx.x * blockDim.x + threadIdx.x;
    if (i >= n8) return;
    const float4* s = reinterpret_cast<const float4*>(src) + i * 2;
    float4 a = __ldg(s), b = __ldg(s + 1);
    uint4 o;
    o.x = (uint32_t)__bfloat16_as_ushort(__float2bfloat16_rn(a.x)) |
          ((uint32_t)__bfloat16_as_ushort(__float2bfloat16_rn(a.y)) << 16);
    o.y = (uint32_t)__bfloat16_as_ushort(__float2bfloat16_rn(a.z)) |
          ((uint32_t)__bfloat16_as_ushort(__float2bfloat16_rn(a.w)) << 16);
    o.z = (uint32_t)__bfloat16_as_ushort(__float2bfloat16_rn(b.x)) |
          ((uint32_t)__bfloat16_as_ushort(__float2bfloat16_rn(b.y)) << 16);
    o.w = (uint32_t)__bfloat16_as_ushort(__float2bfloat16_rn(b.z)) |
          ((uint32_t)__bfloat16_as_ushort(__float2bfloat16_rn(b.w)) << 16);
    reinterpret_cast<uint4*>(dst)[i] = o;
}

// ---------------- HMMA filter: dot-max + candidate collection ----------------
#define PITCH 80          // bytes per 32-col bf16 row (64B data + 16B pad)
#define TILE_BYTES (128 * PITCH)

__global__ __launch_bounds__(256, 2) void mma_filter() {
    __shared__ char sA[2][TILE_BYTES];
    __shared__ char sB[2][TILE_BYTES];
    __shared__ unsigned rmax[128];

    int tid = threadIdx.x, lid = tid & 31, wid = tid >> 5;
    int wm = wid >> 2, wn = wid & 3;     // warp grid 2 (m) x 4 (n)
    int m0 = blockIdx.x * 128;

    if (tid < 128) rmax[tid] = 0u;

    uint32_t aB0 = smem_u32(sA[0]), aB1 = smem_u32(sA[1]);
    uint32_t bB0 = smem_u32(sB[0]), bB1 = smem_u32(sB[1]);

    int r0 = tid >> 2, c0 = tid & 3;
    int r1 = (tid + 256) >> 2, c1 = (tid + 256) & 3;

    int lt = lid >> 3, l8 = lid & 7;
    int a_row_off = l8 + (lt & 1) * 8;
    int a_col_off = (lt >> 1) * 8;
    int b_row_off = l8;
    int b_col_off = (lt & 1) * 8;

    int g = lid >> 2, tc = (lid & 3) * 2;

    for (int ntile = 0; ntile < 64; ntile++) {
        int n0 = ntile * 128;
        float acc[4][4][4];
#pragma unroll
        for (int mt = 0; mt < 4; mt++)
#pragma unroll
            for (int nt = 0; nt < 4; nt++)
#pragma unroll
                for (int q = 0; q < 4; q++) acc[mt][nt][q] = 0.f;

        cp16(aB0 + r0 * PITCH + c0 * 16, g_zb + (size_t)(m0 + r0) * ND + c0 * 8);
        cp16(aB0 + r1 * PITCH + c1 * 16, g_zb + (size_t)(m0 + r1) * ND + c1 * 8);
        cp16(bB0 + r0 * PITCH + c0 * 16, g_wb + (size_t)(n0 + r0) * ND + c0 * 8);
        cp16(bB0 + r1 * PITCH + c1 * 16, g_wb + (size_t)(n0 + r1) * ND + c1 * 8);
        cp_commit();

        for (int kb = 0; kb < 16; kb++) {
            if (kb < 15) {
                int kk = (kb + 1) * 32;
                uint32_t aN = ((kb + 1) & 1) ? aB1 : aB0;
                uint32_t bN = ((kb + 1) & 1) ? bB1 : bB0;
                cp16(aN + r0 * PITCH + c0 * 16, g_zb + (size_t)(m0 + r0) * ND + kk + c0 * 8);
                cp16(aN + r1 * PITCH + c1 * 16, g_zb + (size_t)(m0 + r1) * ND + kk + c1 * 8);
                cp16(bN + r0 * PITCH + c0 * 16, g_wb + (size_t)(n0 + r0) * ND + kk + c0 * 8);
                cp16(bN + r1 * PITCH + c1 * 16, g_wb + (size_t)(n0 + r1) * ND + kk + c1 * 8);
                cp_commit();
                cp_wait<1>();
            } else {
                cp_wait<0>();
            }
            __syncthreads();

            uint32_t aCur = (kb & 1) ? aB1 : aB0;
            uint32_t bCur = (kb & 1) ? bB1 : bB0;
#pragma unroll
            for (int ks = 0; ks < 2; ks++) {
                uint32_t af[4][4], bf[4][2];
#pragma unroll
                for (int mt = 0; mt < 4; mt++) {
                    int row = wm * 64 + mt * 16 + a_row_off;
                    int col = ks * 16 + a_col_off;
                    ldmA(af[mt], aCur + row * PITCH + col * 2);
                }
#pragma unroll
                for (int nt = 0; nt < 4; nt++) {
                    int row = wn * 32 + nt * 8 + b_row_off;
                    int col = ks * 16 + b_col_off;
                    ldmB(bf[nt], bCur + row * PITCH + col * 2);
                }
#pragma unroll
                for (int mt = 0; mt < 4; mt++)
#pragma unroll
                    for (int nt = 0; nt < 4; nt++)
                        mma16816(acc[mt][nt], af[mt], bf[nt]);
            }
            __syncthreads();
        }

        // epilogue: running row-max + candidate collection (superset-safe)
#pragma unroll
        for (int mt = 0; mt < 4; mt++) {
#pragma unroll
            for (int h = 0; h < 2; h++) {
                float m8 = -1e30f;
#pragma unroll
                for (int nt = 0; nt < 4; nt++)
                    m8 = fmaxf(m8, fmaxf(acc[mt][nt][h * 2], acc[mt][nt][h * 2 + 1]));
                int r = wm * 64 + mt * 16 + h * 8 + g;
                unsigned old = atomicMax(&rmax[r], fkey(m8));
                float cur = fmaxf(m8, fdec(old));   // fdec(0)=NaN -> fmaxf picks m8
                float th = cur - MARGIN_S;
                int grow = m0 + r;
#pragma unroll
                for (int nt = 0; nt < 4; nt++)
#pragma unroll
                    for (int cc = 0; cc < 2; cc++) {
                        float v = acc[mt][nt][h * 2 + cc];
                        if (v >= th) {
                            int slot = atomicAdd(&g_cnt[grow], 1);
                            if (slot < CAP)
                                g_cand[grow * CAP + slot] = n0 + wn * 32 + nt * 8 + tc + cc;
                        }
                    }
            }
        }
    }
}

// ---------------- exact rescoring (reference rounding) ----------------
// One warp per z-row, z staged in smem. BUGFIX vs round 3: candidates are
// processed in lane-strided batches so ALL cnt (<=CAP) are rescored, not
// just the first 32.
__global__ __launch_bounds__(256) void exact_pass(const float* __restrict__ z,
                                                  const float* __restrict__ W) {
    __shared__ float zs[8][ND];
    int wrp = threadIdx.x >> 5, lid = threadIdx.x & 31;
    int row = blockIdx.x * 8 + wrp;
    if (row >= NB) return;

    float4* zd = reinterpret_cast<float4*>(zs[wrp]);
    const float4* zsrc = reinterpret_cast<const float4*>(z + (size_t)row * ND);
#pragma unroll
    for (int i = 0; i < ND / 4 / 32; i++) zd[lid + i * 32] = __ldg(zsrc + lid + i * 32);
    __syncwarp();

    int cnt = g_cnt[row];
    float zn = g_znorm[row];
    float best = __int_as_float(0x7f800000);
    int bi = 0x7fffffff;

    if (cnt <= CAP) {
        for (int s = lid; s < cnt; s += 32) {
            int k = g_cand[row * CAP + s];
            const float4* wr = reinterpret_cast<const float4*>(W + (size_t)k * ND);
            float acc = 0.f;
#pragma unroll 4
            for (int d = 0; d < ND / 4; d++) {
                float4 wv = __ldg(wr + d);
                float4 zv = zd[d];
                acc = __fmaf_rn(zv.x, wv.x, acc);
                acc = __fmaf_rn(zv.y, wv.y, acc);
                acc = __fmaf_rn(zv.z, wv.z, acc);
                acc = __fmaf_rn(zv.w, wv.w, acc);
            }
            float d2 = __fsub_rn(__fadd_rn(zn, g_wnorm[k]), __fmul_rn(2.0f, acc));
            if (d2 < best || (d2 == best && k < bi)) { best = d2; bi = k; }
        }
    } else {
        // rare fallback: exact full scan
        for (int k = lid; k < NK; k += 32) {
            const float4* wr = reinterpret_cast<const float4*>(W + (size_t)k * ND);
            float acc = 0.f;
#pragma unroll 4
            for (int d = 0; d < ND / 4; d++) {
                float4 wv = __ldg(wr + d);
                float4 zv = zd[d];
                acc = __fmaf_rn(zv.x, wv.x, acc);
                acc = __fmaf_rn(zv.y, wv.y, acc);
                acc = __fmaf_rn(zv.z, wv.z, acc);
                acc = __fmaf_rn(zv.w, wv.w, acc);
            }
            float d2 = __fsub_rn(__fadd_rn(zn, g_wnorm[k]), __fmul_rn(2.0f, acc));
            if (d2 < best || (d2 == best && k < bi)) { best = d2; bi = k; }
        }
    }
#pragma unroll
    for (int off = 16; off > 0; off >>= 1) {
        float ov = __shfl_down_sync(0xffffffffu, best, off);
        int oi = __shfl_down_sync(0xffffffffu, bi, off);
        if (ov < best || (ov == best && oi < bi)) { best = ov; bi = oi; }
    }
    if (lid == 0) g_bestidx[row] = bi;
}

// ---------------- gather + loss ----------------
__global__ void gather_out(const float* __restrict__ z, const float* __restrict__ W,
                           float* __restrict__ out, int out_size) {
    int b = blockIdx.x, t = threadIdx.x;
    int idx = g_bestidx[b];
    const float* wr = W + (size_t)idx * ND;
    const float* zr = z + (size_t)b * ND;
    float s = 0.f;
#pragma unroll
    for (int i = 0; i < ND / 128; i++) {
        int j = t + i * 128;
        float wv = wr[j], zv = zr[j];
        float diff = __fsub_rn(wv, zv);
        out[(size_t)b * ND + j] = __fadd_rn(zv, diff);
        s = __fmaf_rn(diff, diff, s);
    }
    __shared__ float sm[128];
    sm[t] = s;
    __syncthreads();
    for (int o = 64; o > 0; o >>= 1) {
        if (t < o) sm[t] += sm[t + o];
        __syncthreads();
    }
    if (t == 0) {
        g_partials[b] = sm[0];
        size_t off = (size_t)NB * ND + b;
        if (off < (size_t)out_size) out[off] = (float)idx;
    }
}
__global__ void loss_reduce(float* __restrict__ out, int out_size) {
    __shared__ float sm[256];
    int t = threadIdx.x;
    float s = 0.f;
    for (int i = t; i < NB; i += 256) s += g_partials[i];
    sm[t] = s;
    __syncthreads();
    for (int o = 128; o > 0; o >>= 1) {
        if (t < o) sm[t] += sm[t + o];
        __syncthreads();
    }
    if (t == 0) {
        size_t off = (size_t)NB * ND + NB;
        if (off < (size_t)out_size)
            out[off] = 1.25f * (sm[0] / (float)((size_t)NB * ND));
    }
}

// ---------------- launch ----------------
extern "C" void kernel_launch(void* const* d_in, const int* in_sizes, int n_in,
                              void* d_out, int out_size) {
    const float* z = (const float*)d_in[0];
    const float* W = (const float*)d_in[1];
    float* out = (float*)d_out;

    unsigned short* zb_ptr = nullptr;
    unsigned short* wb_ptr = nullptr;
    cudaGetSymbolAddress((void**)&zb_ptr, g_zb);
    cudaGetSymbolAddress((void**)&wb_ptr, g_wb);

    rownorm_z<<<NB / 128, 128>>>(z);
    rownorm_w<<<NK / 128, 128>>>(W);
    conv_bf16<<<(NB * ND / 8 + 255) / 256, 256>>>(z, zb_ptr, NB * ND / 8);
    conv_bf16<<<(NK * ND / 8 + 255) / 256, 256>>>(W, wb_ptr, NK * ND / 8);
    mma_filter<<<NB / 128, 256>>>();
    exact_pass<<<NB / 8, 256>>>(z, W);
    gather_out<<<NB, 128>>>(z, W, out, out_size);
    loss_reduce<<<1, 256>>>(out, out_size);
}